// round 17
// baseline (speedup 1.0000x reference)
#include <cuda_runtime.h>
#include <cuda_bf16.h>
#include <math.h>
#include <stdint.h>

#define NTOT (8*64*256*256)

// ---------------- scratch ----------------
__device__ __nv_bfloat16 d_BpH[512*256*128], d_BpL[512*256*128];  // K1 out [bc][h][2ky+c]
__device__ float2        d_Xf [512*128*64];                       // x_ft corners [bc][kx][ky]
__device__ __nv_bfloat16 d_OfH[512*128*128], d_OfL[512*128*128];  // spectral out [bo][kx][2ky+c]
__device__ __nv_bfloat16 d_ZreH[512*256*64], d_ZreL[512*256*64];  // inv-H out, split re
__device__ __nv_bfloat16 d_ZimH[512*256*64], d_ZimL[512*256*64];  // inv-H out, split im
// bf16-split twiddle tables
__device__ __nv_bfloat16 d_FW2hi [256*128], d_FW2lo [256*128];
__device__ __nv_bfloat16 d_FH2hi [128*512], d_FH2lo [128*512];
__device__ __nv_bfloat16 d_FHI2hi[256*256], d_FHI2lo[256*256];
__device__ __nv_bfloat16 d_TCh[64*128], d_TCl[64*128];            // scaled cos [ky][w<128]
__device__ __nv_bfloat16 d_TSh[64*128], d_TSl[64*128];            // scaled sin [ky][w<128]
// spectral weights
__device__ float2 d_wt [2*256*64*64];
__device__ float2 d_lbt[2*15*256*4*64];
__device__ float2 d_la [2*15*4*64];
__device__ float  d_gate[30];

__device__ __forceinline__ void cfma(float2& c, float2 a, float2 b) {
    c.x = fmaf(a.x, b.x, c.x); c.x = fmaf(-a.y, b.y, c.x);
    c.y = fmaf(a.x, b.y, c.y); c.y = fmaf( a.y, b.x, c.y);
}
__device__ __forceinline__ void split2(float a, float b, __nv_bfloat162& h, __nv_bfloat162& l) {
    __nv_bfloat16 ha = __float2bfloat16(a), hb = __float2bfloat16(b);
    h.x = ha; h.y = hb;
    l.x = __float2bfloat16(a - __bfloat162float(ha));
    l.y = __float2bfloat16(b - __bfloat162float(hb));
}
__device__ __forceinline__ void store_split2(__nv_bfloat16* H, __nv_bfloat16* L,
                                             size_t idx, float a, float b) {
    __nv_bfloat162 h, l; split2(a, b, h, l);
    *(__nv_bfloat162*)(H + idx) = h;
    *(__nv_bfloat162*)(L + idx) = l;
}
__device__ __forceinline__ void store_split1(__nv_bfloat16* H, __nv_bfloat16* L,
                                             size_t idx, float v) {
    __nv_bfloat16 h = __float2bfloat16(v);
    H[idx] = h;
    L[idx] = __float2bfloat16(v - __bfloat162float(h));
}

__device__ __forceinline__ void ldsm4(uint32_t addr, uint32_t& r0, uint32_t& r1, uint32_t& r2, uint32_t& r3) {
    asm volatile("ldmatrix.sync.aligned.m8n8.x4.shared.b16 {%0,%1,%2,%3}, [%4];"
                 : "=r"(r0), "=r"(r1), "=r"(r2), "=r"(r3) : "r"(addr));
}
__device__ __forceinline__ void ldsm4t(uint32_t addr, uint32_t& r0, uint32_t& r1, uint32_t& r2, uint32_t& r3) {
    asm volatile("ldmatrix.sync.aligned.m8n8.x4.trans.shared.b16 {%0,%1,%2,%3}, [%4];"
                 : "=r"(r0), "=r"(r1), "=r"(r2), "=r"(r3) : "r"(addr));
}
__device__ __forceinline__ void mma16816(float* c, const uint32_t* a, const uint32_t* b) {
    asm volatile("mma.sync.aligned.m16n8k16.row.col.f32.bf16.bf16.f32 "
                 "{%0,%1,%2,%3},{%4,%5,%6,%7},{%8,%9},{%0,%1,%2,%3};"
                 : "+f"(c[0]), "+f"(c[1]), "+f"(c[2]), "+f"(c[3])
                 : "r"(a[0]), "r"(a[1]), "r"(a[2]), "r"(a[3]), "r"(b[0]), "r"(b[1]));
}

// ---------------- table init ----------------
__global__ void init_tabs2_k() {
    int id = blockIdx.x * 256 + threadIdx.x;   // 196608 launched; used < 180224
    const float S = 6.283185307179586f / 256.0f;
    float v; __nv_bfloat16 *hi, *lo; int idx;
    if (id < 32768) {                          // FW2 [w][2ky+c]
        int w = id >> 7, n = id & 127, ky = n >> 1;
        float a = S * (float)((w * ky) & 255);
        v = (n & 1) ? -sinf(a) : cosf(a);
        hi = d_FW2hi; lo = d_FW2lo; idx = id;
    } else if (id < 98304) {                   // FH2 [kxIdx][2h+d]
        int r = id - 32768; int m = r >> 9, q = r & 511;
        int h = q >> 1, dd = q & 1;
        int kx = (m < 64) ? m : m + 128;
        float a = S * (float)((kx * h) & 255);
        v = dd ? -sinf(a) : cosf(a);
        hi = d_FH2hi; lo = d_FH2lo; idx = r;
    } else if (id < 163840) {                  // FHI2 [h][2kxIdx+d]
        int r = id - 98304; int h = r >> 8, q = r & 255;
        int kxi = q >> 1, dd = q & 1;
        int kx = (kxi < 64) ? kxi : kxi + 128;
        float a = S * (float)((kx * h) & 255);
        v = dd ? sinf(a) : cosf(a);
        hi = d_FHI2hi; lo = d_FHI2lo; idx = r;
    } else if (id < 172032) {                  // TC [ky][w], scaled
        int r = id - 163840; int ky = r >> 7, w = r & 127;
        float s = ((ky == 0) ? 1.f : 2.f) * (1.f / 65536.f);
        v = s * cosf(S * (float)((ky * w) & 255));
        hi = d_TCh; lo = d_TCl; idx = r;
    } else if (id < 180224) {                  // TS [ky][w], scaled
        int r = id - 172032; int ky = r >> 7, w = r & 127;
        float s = ((ky == 0) ? 1.f : 2.f) * (1.f / 65536.f);
        v = s * sinf(S * (float)((ky * w) & 255));
        hi = d_TSh; lo = d_TSl; idx = r;
    } else return;
    __nv_bfloat16 h16 = __float2bfloat16(v);
    hi[idx] = h16;
    lo[idx] = __float2bfloat16(v - __bfloat162float(h16));
}

__global__ void init_wt_k(const float* __restrict__ w1re, const float* __restrict__ w1im,
                          const float* __restrict__ w2re, const float* __restrict__ w2im) {
    int id = blockIdx.x * 256 + threadIdx.x;
    if (id >= 2 * 256 * 4096) return;
    int t = id >> 20, rem = id & 1048575;
    int p = rem >> 12, io = rem & 4095;
    int i = io >> 6, o = io & 63;
    const float* re = t ? w2re : w1re;
    const float* im = t ? w2im : w1im;
    size_t src = ((size_t)(i * 64 + o)) * 256 + p;
    d_wt[id] = make_float2(re[src], im[src]);
}

__global__ void init_lbt_k(const float* __restrict__ b1re, const float* __restrict__ b1im,
                           const float* __restrict__ b2re, const float* __restrict__ b2im) {
    int id = blockIdx.x * 256 + threadIdx.x;
    if (id >= 2 * 15 * 256 * 256) return;
    int t = id / 983040, rem = id % 983040;
    int e = rem >> 16, rem2 = rem & 65535;
    int p = rem2 >> 8, ro = rem2 & 255;
    int r = ro >> 6, o = ro & 63;
    const float* re = t ? b2re : b1re;
    const float* im = t ? b2im : b1im;
    size_t src = (((size_t)(e * 64 + o)) * 4 + r) * 256 + p;
    d_lbt[id] = make_float2(re[src], im[src]);
}

__global__ void init_small_k(const float* __restrict__ la1re, const float* __restrict__ la1im,
                             const float* __restrict__ la2re, const float* __restrict__ la2im,
                             const float* __restrict__ g1, const float* __restrict__ g2,
                             float* sp_out) {
    int tid = threadIdx.x;
    for (int id = tid; id < 7680; id += 256) {
        int t = id / 3840, rem = id % 3840;
        const float* re = t ? la2re : la1re;
        const float* im = t ? la2im : la1im;
        d_la[id] = make_float2(re[rem], im[rem]);
    }
    __shared__ float gs[30];
    if (tid < 30) {
        float v = (tid < 15) ? g1[tid] : g2[tid - 15];
        float s = 1.0f / (1.0f + expf(-v));
        d_gate[tid] = s; gs[tid] = s;
    }
    __syncthreads();
    if (tid == 0 && sp_out) {
        float s = 0.0f;
        for (int i = 0; i < 30; i++) s += gs[i];
        *sp_out = s / 15.0f;
    }
}

// ---------------- unified bf16-split tensor-core GEMM, double-buffered ----------------
// BM=128, BN=128, BK=32, 512 threads (16 warps, 4x4), warp tile 32x32.
// STAGE 0: C = x * FW2            -> BpH/L      (M=131072, K=256, N=128)
// STAGE 1: C = FH2 * dup(Bp[bc])  -> Xf         (M=128,    K=512, N=128)
// STAGE 2: C = FHI2 * dup(Of[bo]) -> Zre/Zim    (M=256,    K=256, N=128)
#define ASZ  (128*40)
#define BSZ  (32*136)
#define ASZB (ASZ*2)
#define BSZB (BSZ*2)
#define BUFE (2*ASZ + 2*BSZ)
#define BUFB (BUFE*2)
#define SMEM_BYTES (2*BUFB)

template<int STAGE, int KDIM, int LDB>
__global__ __launch_bounds__(512) void mma_gemm_k(const float* __restrict__ xin,
                                                  float* __restrict__ yout) {
    constexpr bool AFP32 = (STAGE == 0);
    constexpr bool BEXP  = (STAGE == 1 || STAGE == 2);
    constexpr int NI = KDIM / 32;
    extern __shared__ __align__(16) __nv_bfloat16 smem[];
    int tid = threadIdx.x, lane = tid & 31, warp = tid >> 5;
    int mw = (warp >> 2) * 32, nw = (warp & 3) * 32;
    int g = lane >> 3, lr = lane & 7;
    int f_row = (g & 1) * 8 + lr;
    int f_col = (g >> 1) * 8;

    int m0 = 0, n0 = 0, bat = 0;
    if constexpr (STAGE == 0) { m0 = blockIdx.x * 128; }
    if constexpr (STAGE == 1) { bat = blockIdx.x; }
    if constexpr (STAGE == 2) { bat = blockIdx.x; m0 = blockIdx.y * 128; }

    const __nv_bfloat16 *AhG = nullptr, *AlG = nullptr, *BhG = nullptr, *BlG = nullptr;
    size_t boff = 0;
    if constexpr (STAGE == 0) { BhG = d_FW2hi;  BlG = d_FW2lo; }
    if constexpr (STAGE == 1) { AhG = d_FH2hi;  AlG = d_FH2lo;  BhG = d_BpH; BlG = d_BpL; boff = (size_t)bat * 32768; }
    if constexpr (STAGE == 2) { AhG = d_FHI2hi; AlG = d_FHI2lo; BhG = d_OfH; BlG = d_OfL; boff = (size_t)bat * 16384; }

    int arow = tid >> 2, acb = (tid & 3) * 8;
    int brow = tid >> 4, bcb = (tid & 15) * 8;
    int bdup = brow & 1;

    float c[2][4][4] = {};
    uint32_t sbase = (uint32_t)__cvta_generic_to_shared(smem);
    uint4 pa0, pa1, pb0, pb1;

    auto loadT = [&](int k0, uint4& a0, uint4& a1, uint4& b0, uint4& b1) {
        if constexpr (AFP32) {
            const float* ap = xin + (size_t)(m0 + arow) * KDIM + k0 + acb;
            a0 = ((const uint4*)ap)[0]; a1 = ((const uint4*)ap)[1];
        } else {
            size_t src = (size_t)(m0 + arow) * KDIM + k0 + acb;
            a0 = *(const uint4*)(AhG + src);
            a1 = *(const uint4*)(AlG + src);
        }
        if constexpr (BEXP) {
            int h = (k0 + brow) >> 1;
            b0 = *(const uint4*)(BhG + boff + (size_t)h * 128 + bcb);
            b1 = *(const uint4*)(BlG + boff + (size_t)h * 128 + bcb);
        } else {
            size_t src = (size_t)(k0 + brow) * LDB + n0 + bcb;
            b0 = *(const uint4*)(BhG + src);
            b1 = *(const uint4*)(BlG + src);
        }
    };
    auto storeT = [&](int buf, uint4 a0, uint4 a1, uint4 b0, uint4 b1) {
        __nv_bfloat16* Ah = smem + buf * BUFE;
        __nv_bfloat16* Al = Ah + ASZ;
        __nv_bfloat16* Bh = Al + ASZ;
        __nv_bfloat16* Bl = Bh + BSZ;
        if constexpr (AFP32) {
            float4 v0 = *(float4*)&a0, v1 = *(float4*)&a1;
            __nv_bfloat162 h0, l0, h1, l1, h2, l2, h3, l3;
            split2(v0.x, v0.y, h0, l0); split2(v0.z, v0.w, h1, l1);
            split2(v1.x, v1.y, h2, l2); split2(v1.z, v1.w, h3, l3);
            int o = arow * 40 + acb;
            *(__nv_bfloat162*)&Ah[o]     = h0; *(__nv_bfloat162*)&Ah[o + 2] = h1;
            *(__nv_bfloat162*)&Ah[o + 4] = h2; *(__nv_bfloat162*)&Ah[o + 6] = h3;
            *(__nv_bfloat162*)&Al[o]     = l0; *(__nv_bfloat162*)&Al[o + 2] = l1;
            *(__nv_bfloat162*)&Al[o + 4] = l2; *(__nv_bfloat162*)&Al[o + 6] = l3;
        } else {
            *(uint4*)&Ah[arow * 40 + acb] = a0;
            *(uint4*)&Al[arow * 40 + acb] = a1;
        }
        if constexpr (BEXP) {
            uint32_t* dh = (uint32_t*)&Bh[brow * 136 + bcb];
            uint32_t* dl = (uint32_t*)&Bl[brow * 136 + bcb];
            const uint32_t* sh = (const uint32_t*)&b0;
            const uint32_t* sl = (const uint32_t*)&b1;
#pragma unroll
            for (int i = 0; i < 4; i++) {
                uint32_t uh = sh[i], ul = sl[i];
                if (bdup) {
                    uh = (uh << 16) | ((uh >> 16) ^ 0x8000u);
                    ul = (ul << 16) | ((ul >> 16) ^ 0x8000u);
                }
                dh[i] = uh; dl[i] = ul;
            }
        } else {
            *(uint4*)&Bh[brow * 136 + bcb] = b0;
            *(uint4*)&Bl[brow * 136 + bcb] = b1;
        }
    };

    loadT(0, pa0, pa1, pb0, pb1);
    storeT(0, pa0, pa1, pb0, pb1);
    __syncthreads();

#pragma unroll 1
    for (int i = 0; i < NI; i++) {
        int cur = i & 1;
        bool more = (i + 1 < NI);
        if (more) loadT((i + 1) * 32, pa0, pa1, pb0, pb1);

        uint32_t sAh = sbase + cur * BUFB;
        uint32_t sAl = sAh + ASZB;
        uint32_t sBh = sAl + ASZB;
        uint32_t sBl = sBh + BSZB;
#pragma unroll
        for (int ks = 0; ks < 2; ks++) {
            int koff = ks * 16;
            uint32_t ah[2][4], al[2][4];
#pragma unroll
            for (int mi = 0; mi < 2; mi++) {
                uint32_t off = (uint32_t)(((mw + mi * 16 + f_row) * 40 + koff + f_col) * 2);
                ldsm4(sAh + off, ah[mi][0], ah[mi][1], ah[mi][2], ah[mi][3]);
                ldsm4(sAl + off, al[mi][0], al[mi][1], al[mi][2], al[mi][3]);
            }
            uint32_t bh[4][2], bl[4][2];
#pragma unroll
            for (int p = 0; p < 2; p++) {
                uint32_t off = (uint32_t)(((koff + f_row) * 136 + nw + p * 16 + f_col) * 2);
                uint32_t r0, r1, r2, r3;
                ldsm4t(sBh + off, r0, r1, r2, r3);
                bh[2*p][0] = r0; bh[2*p][1] = r1; bh[2*p+1][0] = r2; bh[2*p+1][1] = r3;
                ldsm4t(sBl + off, r0, r1, r2, r3);
                bl[2*p][0] = r0; bl[2*p][1] = r1; bl[2*p+1][0] = r2; bl[2*p+1][1] = r3;
            }
#pragma unroll
            for (int mi = 0; mi < 2; mi++)
#pragma unroll
                for (int ni = 0; ni < 4; ni++) {
                    mma16816(c[mi][ni], ah[mi], bh[ni]);
                    mma16816(c[mi][ni], ah[mi], bl[ni]);
                    mma16816(c[mi][ni], al[mi], bh[ni]);
                }
        }
        if (more) storeT(1 - cur, pa0, pa1, pb0, pb1);
        __syncthreads();
    }

#pragma unroll
    for (int mi = 0; mi < 2; mi++)
#pragma unroll
        for (int ni = 0; ni < 4; ni++) {
            int gm = m0 + mw + mi * 16 + (lane >> 2);
            int gn = n0 + nw + ni * 8 + (lane & 3) * 2;
            float v0 = c[mi][ni][0], v1 = c[mi][ni][1];
            float v2 = c[mi][ni][2], v3 = c[mi][ni][3];
            if constexpr (STAGE == 0) {
                store_split2(d_BpH, d_BpL, (size_t)gm * 128 + gn, v0, v1);
                store_split2(d_BpH, d_BpL, (size_t)(gm + 8) * 128 + gn, v2, v3);
            } else if constexpr (STAGE == 1) {
                float2* C2 = d_Xf + (size_t)bat * 8192;
                C2[gm * 64 + (gn >> 1)]       = make_float2(v0, v1);
                C2[(gm + 8) * 64 + (gn >> 1)] = make_float2(v2, v3);
            } else {
                int ky = gn >> 1;
                size_t zb  = (size_t)(bat * 256 + gm) * 64 + ky;
                size_t zb2 = zb + 8 * 64;
                store_split1(d_ZreH, d_ZreL, zb,  v0);
                store_split1(d_ZimH, d_ZimL, zb,  v1);
                store_split1(d_ZreH, d_ZreL, zb2, v2);
                store_split1(d_ZimH, d_ZimL, zb2, v3);
            }
        }
}

// ---------------- K6 folded: P = Zre*cos, Q = Zim*sin; y[w]=P-Q, y[256-w]=P+Q ----------------
__global__ __launch_bounds__(512) void k6fold_k(float* __restrict__ yout) {
    extern __shared__ __align__(16) __nv_bfloat16 smem[];
    int tid = threadIdx.x, lane = tid & 31, warp = tid >> 5;
    int mw = (warp >> 2) * 32, nw = (warp & 3) * 32;
    int g = lane >> 3, lr = lane & 7;
    int f_row = (g & 1) * 8 + lr;
    int f_col = (g >> 1) * 8;
    int m0 = blockIdx.x * 128;

    int arow = tid >> 2, acb = (tid & 3) * 8;
    int brow = tid >> 4, bcb = (tid & 15) * 8;

    float cP[2][4][4] = {}, cQ[2][4][4] = {};
    uint32_t sbase = (uint32_t)__cvta_generic_to_shared(smem);
    uint4 pa0, pa1, pb0, pb1;

    // iter i in 0..3: phase = i>>1 (0:P re/cos, 1:Q im/sin), k0 = (i&1)*32
    auto loadT = [&](int i, uint4& a0, uint4& a1, uint4& b0, uint4& b1) {
        int ph = i >> 1, k0 = (i & 1) * 32;
        const __nv_bfloat16* AH = ph ? d_ZimH : d_ZreH;
        const __nv_bfloat16* AL = ph ? d_ZimL : d_ZreL;
        const __nv_bfloat16* BH = ph ? d_TSh : d_TCh;
        const __nv_bfloat16* BL = ph ? d_TSl : d_TCl;
        size_t asrc = (size_t)(m0 + arow) * 64 + k0 + acb;
        a0 = *(const uint4*)(AH + asrc);
        a1 = *(const uint4*)(AL + asrc);
        size_t bsrc = (size_t)(k0 + brow) * 128 + bcb;
        b0 = *(const uint4*)(BH + bsrc);
        b1 = *(const uint4*)(BL + bsrc);
    };
    auto storeT = [&](int buf, uint4 a0, uint4 a1, uint4 b0, uint4 b1) {
        __nv_bfloat16* Ah = smem + buf * BUFE;
        __nv_bfloat16* Al = Ah + ASZ;
        __nv_bfloat16* Bh = Al + ASZ;
        __nv_bfloat16* Bl = Bh + BSZ;
        *(uint4*)&Ah[arow * 40 + acb] = a0;
        *(uint4*)&Al[arow * 40 + acb] = a1;
        *(uint4*)&Bh[brow * 136 + bcb] = b0;
        *(uint4*)&Bl[brow * 136 + bcb] = b1;
    };

    loadT(0, pa0, pa1, pb0, pb1);
    storeT(0, pa0, pa1, pb0, pb1);
    __syncthreads();

#pragma unroll 1
    for (int i = 0; i < 4; i++) {
        int cur = i & 1;
        bool more = (i + 1 < 4);
        if (more) loadT(i + 1, pa0, pa1, pb0, pb1);

        float (*acc)[4][4] = (i >> 1) ? cQ : cP;
        uint32_t sAh = sbase + cur * BUFB;
        uint32_t sAl = sAh + ASZB;
        uint32_t sBh = sAl + ASZB;
        uint32_t sBl = sBh + BSZB;
#pragma unroll
        for (int ks = 0; ks < 2; ks++) {
            int koff = ks * 16;
            uint32_t ah[2][4], al[2][4];
#pragma unroll
            for (int mi = 0; mi < 2; mi++) {
                uint32_t off = (uint32_t)(((mw + mi * 16 + f_row) * 40 + koff + f_col) * 2);
                ldsm4(sAh + off, ah[mi][0], ah[mi][1], ah[mi][2], ah[mi][3]);
                ldsm4(sAl + off, al[mi][0], al[mi][1], al[mi][2], al[mi][3]);
            }
            uint32_t bh[4][2], bl[4][2];
#pragma unroll
            for (int p = 0; p < 2; p++) {
                uint32_t off = (uint32_t)(((koff + f_row) * 136 + nw + p * 16 + f_col) * 2);
                uint32_t r0, r1, r2, r3;
                ldsm4t(sBh + off, r0, r1, r2, r3);
                bh[2*p][0] = r0; bh[2*p][1] = r1; bh[2*p+1][0] = r2; bh[2*p+1][1] = r3;
                ldsm4t(sBl + off, r0, r1, r2, r3);
                bl[2*p][0] = r0; bl[2*p][1] = r1; bl[2*p+1][0] = r2; bl[2*p+1][1] = r3;
            }
#pragma unroll
            for (int mi = 0; mi < 2; mi++)
#pragma unroll
                for (int ni = 0; ni < 4; ni++) {
                    mma16816(acc[mi][ni], ah[mi], bh[ni]);
                    mma16816(acc[mi][ni], ah[mi], bl[ni]);
                    mma16816(acc[mi][ni], al[mi], bh[ni]);
                }
        }
        if (more) storeT(1 - cur, pa0, pa1, pb0, pb1);
        __syncthreads();
    }

#pragma unroll
    for (int mi = 0; mi < 2; mi++)
#pragma unroll
        for (int ni = 0; ni < 4; ni++) {
            int gm = m0 + mw + mi * 16 + (lane >> 2);
            int gn = nw + ni * 8 + (lane & 3) * 2;   // w in [0,128)
            float p0 = cP[mi][ni][0], p1 = cP[mi][ni][1];
            float p2 = cP[mi][ni][2], p3 = cP[mi][ni][3];
            float q0 = cQ[mi][ni][0], q1 = cQ[mi][ni][1];
            float q2 = cQ[mi][ni][2], q3 = cQ[mi][ni][3];
            float* r0 = yout + (size_t)gm * 256;
            float* r1 = yout + (size_t)(gm + 8) * 256;
            r0[gn] = p0 - q0; r0[gn + 1] = p1 - q1;
            r1[gn] = p2 - q2; r1[gn + 1] = p3 - q3;
            if (gn > 0) { r0[256 - gn] = p0 + q0; r1[256 - gn] = p2 + q2; }
            r0[255 - gn] = p1 + q1;
            r1[255 - gn] = p3 + q3;
        }
}

// w=128 column: y[m][128] = sum_ky Zre[m][ky] * (+/-)scale
__global__ void y128_k(float* __restrict__ out) {
    int m = blockIdx.x * 256 + threadIdx.x;
    const __nv_bfloat16* zh = d_ZreH + (size_t)m * 64;
    const __nv_bfloat16* zl = d_ZreL + (size_t)m * 64;
    float s = (__bfloat162float(zh[0]) + __bfloat162float(zl[0])) * (1.f / 65536.f);
#pragma unroll 8
    for (int k = 1; k < 64; k++) {
        float v = __bfloat162float(zh[k]) + __bfloat162float(zl[k]);
        s = fmaf(v, ((k & 1) ? -2.f : 2.f) * (1.f / 65536.f), s);
    }
    out[(size_t)m * 256 + 128] = s;
}

// ---------------- spectral multiply (fp32; split-store to Of) ----------------
__global__ __launch_bounds__(512) void base_mul_k() {
    int t = blockIdx.x, p = blockIdx.y;
    int x = p >> 4, y = p & 15;
    int kxIdx = (t == 0) ? x : (112 + x);
    int ky = y;
    __shared__ float2 Xs[8][64];
    int tid = threadIdx.x;
    {
        int b = tid >> 6, i = tid & 63;
        Xs[b][i] = d_Xf[(size_t)(b * 64 + i) * 8192 + kxIdx * 64 + ky];
    }
    __syncthreads();
    int o = tid & 63, b = tid >> 6;
    const float2* wp = d_wt + ((size_t)t * 256 + p) * 4096;
    float2 s = {0.f, 0.f};
#pragma unroll 8
    for (int i = 0; i < 64; i++) cfma(s, Xs[b][i], wp[i * 64 + o]);
    size_t idx = (size_t)(b * 64 + o) * 16384 + (size_t)kxIdx * 128 + 2 * ky;
    store_split2(d_OfH, d_OfL, idx, s.x, s.y);
}

__global__ __launch_bounds__(512) void expert_mul_k() {
    int tile = blockIdx.x;
    int half = tile / 15, e = tile % 15;
    int p = blockIdx.y;
    int x = p >> 4, y = p & 15;
    int Rr = (e + 1) >> 2, Cc = (e + 1) & 3;
    int ky = Cc * 16 + y;
    int kxIdx = (half == 0) ? (Rr * 16 + x) : (64 + (3 - Rr) * 16 + x);
    __shared__ float2 Xs[8][64];
    __shared__ float2 Ts[8][4];
    int tid = threadIdx.x;
    {
        int b = tid >> 6, i = tid & 63;
        Xs[b][i] = d_Xf[(size_t)(b * 64 + i) * 8192 + kxIdx * 64 + ky];
    }
    __syncthreads();
    if (tid < 32) {
        int b = tid >> 2, r = tid & 3;
        const float2* lap = d_la + (size_t)(half * 15 + e) * 256 + r * 64;
        float2 s = {0.f, 0.f};
#pragma unroll 8
        for (int i = 0; i < 64; i++) cfma(s, Xs[b][i], lap[i]);
        Ts[b][r] = s;
    }
    __syncthreads();
    int o = tid & 63, b = tid >> 6;
    const float2* lbp = d_lbt + ((size_t)(half * 15 + e) * 256 + p) * 256;
    float2 s = {0.f, 0.f};
#pragma unroll
    for (int r = 0; r < 4; r++) cfma(s, Ts[b][r], lbp[r * 64 + o]);
    float gsc = d_gate[half * 15 + e] * 0.1f;
    s.x *= gsc; s.y *= gsc;
    size_t idx = (size_t)(b * 64 + o) * 16384 + (size_t)kxIdx * 128 + 2 * ky;
    store_split2(d_OfH, d_OfL, idx, s.x, s.y);
}

// ---------------------------------- launch ----------------------------------
extern "C" void kernel_launch(void* const* d_in, const int* in_sizes, int n_in,
                              void* d_out, int out_size) {
    const float* x     = (const float*)d_in[0];
    const float* w1re  = (const float*)d_in[1];
    const float* w1im  = (const float*)d_in[2];
    const float* w2re  = (const float*)d_in[3];
    const float* w2im  = (const float*)d_in[4];
    const float* la1re = (const float*)d_in[5];
    const float* la1im = (const float*)d_in[6];
    const float* lb1re = (const float*)d_in[7];
    const float* lb1im = (const float*)d_in[8];
    const float* la2re = (const float*)d_in[9];
    const float* la2im = (const float*)d_in[10];
    const float* lb2re = (const float*)d_in[11];
    const float* lb2im = (const float*)d_in[12];
    const float* g1    = (const float*)d_in[13];
    const float* g2    = (const float*)d_in[14];
    float* out = (float*)d_out;

    float* sp_out = (out_size > NTOT) ? (out + NTOT) : nullptr;

    static bool attr_set = false;
    if (!attr_set) {
        cudaFuncSetAttribute(mma_gemm_k<0, 256, 128>, cudaFuncAttributeMaxDynamicSharedMemorySize, SMEM_BYTES);
        cudaFuncSetAttribute(mma_gemm_k<1, 512, 128>, cudaFuncAttributeMaxDynamicSharedMemorySize, SMEM_BYTES);
        cudaFuncSetAttribute(mma_gemm_k<2, 256, 128>, cudaFuncAttributeMaxDynamicSharedMemorySize, SMEM_BYTES);
        cudaFuncSetAttribute(k6fold_k, cudaFuncAttributeMaxDynamicSharedMemorySize, SMEM_BYTES);
        attr_set = true;
    }

    init_tabs2_k<<<768, 256>>>();
    init_wt_k<<<8192, 256>>>(w1re, w1im, w2re, w2im);
    init_lbt_k<<<7680, 256>>>(lb1re, lb1im, lb2re, lb2im);
    init_small_k<<<1, 256>>>(la1re, la1im, la2re, la2im, g1, g2, sp_out);

    // K1: rfft along W -> Bp (bf16 hi/lo)
    mma_gemm_k<0, 256, 128><<<dim3(1024), 512, SMEM_BYTES>>>(x, nullptr);
    // K2: fwd H -> Xf
    mma_gemm_k<1, 512, 128><<<dim3(512), 512, SMEM_BYTES>>>(nullptr, nullptr);
    // spectral multiply (fp32 -> Of bf16 hi/lo)
    base_mul_k<<<dim3(2, 256), 512>>>();
    expert_mul_k<<<dim3(30, 256), 512>>>();
    // K5: inv H -> Zre/Zim (bf16 hi/lo)
    mma_gemm_k<2, 256, 128><<<dim3(512, 2), 512, SMEM_BYTES>>>(nullptr, nullptr);
    // K6: folded irfft along W -> out (+ w=128 column)
    k6fold_k<<<dim3(1024), 512, SMEM_BYTES>>>(out);
    y128_k<<<512, 256>>>(out);
}